// round 3
// baseline (speedup 1.0000x reference)
#include <cuda_runtime.h>

#define IMG_H 1080
#define IMG_W 1920
#define PLANE (IMG_H * IMG_W)

// JPEG-style base quant table (row-major 8x8)
__constant__ float c_qbase[64] = {
    16, 11, 10, 16, 24, 40, 51, 61,
    12, 12, 14, 19, 26, 58, 60, 55,
    14, 13, 16, 24, 40, 57, 69, 56,
    14, 17, 22, 29, 51, 87, 80, 62,
    18, 22, 37, 56, 68, 109, 103, 77,
    24, 35, 55, 64, 81, 104, 113, 92,
    49, 64, 78, 87, 103, 121, 120, 101,
    72, 92, 95, 98, 112, 100, 103, 99
};

// DCT-II basis as compile-time constants -> FFMA with immediate operands
#define H1 0.4903926402016152f
#define H2 0.4619397662556434f
#define H3 0.4157348061512726f
#define H4 0.3535533905932738f
#define H5 0.2777851165098011f
#define H6 0.1913417161825449f
#define H7 0.0975451610080641f

__device__ constexpr float BAS[8][8] = {
    { H4,  H4,  H4,  H4,  H4,  H4,  H4,  H4},
    { H1,  H3,  H5,  H7, -H7, -H5, -H3, -H1},
    { H2,  H6, -H6, -H2, -H2, -H6,  H6,  H2},
    { H3, -H7, -H1, -H5,  H5,  H1,  H7, -H3},
    { H4, -H4, -H4,  H4,  H4, -H4, -H4,  H4},
    { H5, -H1,  H7,  H3, -H3, -H7,  H1, -H5},
    { H6, -H2,  H2, -H6, -H6,  H2, -H2,  H6},
    { H7, -H5,  H3, -H1,  H1, -H3,  H5, -H7}
};

__global__ __launch_bounds__(128, 10)
void h264_dct_kernel(const float* __restrict__ x, float* __restrict__ out) {
    // CTA: 128 threads, strip = 8 rows x 128 cols = 16 8x8 blocks.
    // Thread t owns one 8-pixel column. Transforms in registers (immediate
    // basis); smem only for two 8x8 transposes (separate buffers -> 2 BARs).
    // b/g/r are NOT held in registers: the epilogue reloads them (L2-resident
    // by then), which frees ~24 regs and lifts occupancy.
    __shared__ float s1[8][129];  // pad -> conflict-free column reads
    __shared__ float s2[8][129];
    __shared__ float sQ[8][9];

    const int t = threadIdx.x;
    if (t < 64) {
        int k = t >> 3, u = t & 7;
        // QF=28 >= 25 -> scale = 144 ; q = max(base*144/50, 1)
        sQ[k][u] = fmaxf((c_qbase[t] * 144.0f) / 50.0f, 1.0f);
    }

    const int g = t >> 3;         // block index within strip
    const int l = t & 7;          // lane within block
    const int col = blockIdx.x * 128 + t;
    const size_t base = (size_t)blockIdx.z * (3 * (size_t)PLANE)
                      + (size_t)(blockIdx.y * 8) * IMG_W + col;

    float a[8], w[8];

    // Load BGR, form luma column (b/g/r dropped; reloaded at epilogue).
    #pragma unroll
    for (int i = 0; i < 8; ++i) {
        size_t p = base + (size_t)i * IMG_W;
        a[i] = 0.114f * x[p] + 0.587f * x[p + PLANE] + 0.299f * x[p + 2 * PLANE];
    }

    // Vertical DCT (registers)
    #pragma unroll
    for (int k = 0; k < 8; ++k) {
        float acc = 0.0f;
        #pragma unroll
        for (int i = 0; i < 8; ++i) acc = fmaf(BAS[k][i], a[i], acc);
        w[k] = acc;
    }

    // Transpose 1: thread -> owns row l of block g
    #pragma unroll
    for (int k = 0; k < 8; ++k) s1[k][t] = w[k];
    __syncthreads();
    #pragma unroll
    for (int j = 0; j < 8; ++j) a[j] = s1[l][(g << 3) + j];

    // Horizontal DCT + quantize (round-half-even) + horizontal IDCT, registers
    float cq[8];
    #pragma unroll
    for (int u = 0; u < 8; ++u) {
        float acc = 0.0f;
        #pragma unroll
        for (int j = 0; j < 8; ++j) acc = fmaf(a[j], BAS[u][j], acc);
        float q = sQ[l][u];
        cq[u] = rintf(acc / (q + 1e-8f)) * q;
    }
    #pragma unroll
    for (int b = 0; b < 8; ++b) {
        float acc = 0.0f;
        #pragma unroll
        for (int u = 0; u < 8; ++u) acc = fmaf(cq[u], BAS[u][b], acc);
        w[b] = acc;
    }

    // Transpose 2 (separate buffer -> no extra barrier needed before store)
    #pragma unroll
    for (int b = 0; b < 8; ++b) s2[l][(g << 3) + b] = w[b];
    __syncthreads();
    #pragma unroll
    for (int i = 0; i < 8; ++i) a[i] = s2[i][t];

    // Vertical IDCT in registers -> rec column
    float rec[8];
    #pragma unroll
    for (int ar = 0; ar < 8; ++ar) {
        float acc = 0.0f;
        #pragma unroll
        for (int i = 0; i < 8; ++i) acc = fmaf(BAS[i][ar], a[i], acc);
        rec[ar] = acc;
    }

    // Epilogue: reload BGR (hits L2 - lines are still resident), recompute
    // luma (bitwise identical), redistribute delta, clip, streaming-store.
    float rb[8], rg[8], rr[8];
    #pragma unroll
    for (int i = 0; i < 8; ++i) {
        size_t p = base + (size_t)i * IMG_W;
        rb[i] = x[p];
        rg[i] = x[p + PLANE];
        rr[i] = x[p + 2 * PLANE];
    }
    #pragma unroll
    for (int i = 0; i < 8; ++i) {
        float yv = 0.114f * rb[i] + 0.587f * rg[i] + 0.299f * rr[i];
        float yd = rec[i] - yv;
        size_t p = base + (size_t)i * IMG_W;
        __stcs(&out[p],             fminf(fmaxf(rb[i] + 0.114f * yd, 0.0f), 255.0f));
        __stcs(&out[p + PLANE],     fminf(fmaxf(rg[i] + 0.587f * yd, 0.0f), 255.0f));
        __stcs(&out[p + 2 * PLANE], fminf(fmaxf(rr[i] + 0.299f * yd, 0.0f), 255.0f));
    }
}

extern "C" void kernel_launch(void* const* d_in, const int* in_sizes, int n_in,
                              void* d_out, int out_size) {
    const float* x = (const float*)d_in[0];
    float* out = (float*)d_out;

    int B = in_sizes[0] / (3 * PLANE);

    dim3 block(128, 1, 1);
    dim3 grid(IMG_W / 128, IMG_H / 8, B);   // 15 x 135 x B
    h264_dct_kernel<<<grid, block>>>(x, out);
}

// round 4
// speedup vs baseline: 1.0751x; 1.0751x over previous
#include <cuda_runtime.h>

#define IMG_H 1080
#define IMG_W 1920
#define PLANE (IMG_H * IMG_W)

// JPEG-style base quant table (row-major 8x8)
__constant__ float c_qbase[64] = {
    16, 11, 10, 16, 24, 40, 51, 61,
    12, 12, 14, 19, 26, 58, 60, 55,
    14, 13, 16, 24, 40, 57, 69, 56,
    14, 17, 22, 29, 51, 87, 80, 62,
    18, 22, 37, 56, 68, 109, 103, 77,
    24, 35, 55, 64, 81, 104, 113, 92,
    49, 64, 78, 87, 103, 121, 120, 101,
    72, 92, 95, 98, 112, 100, 103, 99
};

// DCT-II basis constants (immediate operands in SASS)
#define H1 0.4903926402016152f
#define H2 0.4619397662556434f
#define H3 0.4157348061512726f
#define H4 0.3535533905932738f
#define H5 0.2777851165098011f
#define H6 0.1913417161825449f
#define H7 0.0975451610080641f

// Forward 8-pt DCT via even/odd butterfly: w[k] = sum_i BAS[k][i] * a[i]
__device__ __forceinline__ void dct8(const float a[8], float w[8]) {
    float s0 = a[0] + a[7], s1 = a[1] + a[6], s2 = a[2] + a[5], s3 = a[3] + a[4];
    float d0 = a[0] - a[7], d1 = a[1] - a[6], d2 = a[2] - a[5], d3 = a[3] - a[4];
    float e0 = s0 + s3, e1 = s1 + s2, f0 = s0 - s3, f1 = s1 - s2;
    w[0] = H4 * (e0 + e1);
    w[4] = H4 * (e0 - e1);
    w[2] = fmaf(H2, f0,  H6 * f1);
    w[6] = fmaf(H6, f0, -H2 * f1);
    w[1] = fmaf(H1, d0, fmaf( H3, d1, fmaf( H5, d2,  H7 * d3)));
    w[3] = fmaf(H3, d0, fmaf(-H7, d1, fmaf(-H1, d2, -H5 * d3)));
    w[5] = fmaf(H5, d0, fmaf(-H1, d1, fmaf( H7, d2,  H3 * d3)));
    w[7] = fmaf(H7, d0, fmaf(-H5, d1, fmaf( H3, d2, -H1 * d3)));
}

// Inverse 8-pt DCT via butterfly: r[n] = sum_k BAS[k][n] * c[k]
__device__ __forceinline__ void idct8(const float c[8], float r[8]) {
    float p = H4 * (c[0] + c[4]);
    float m = H4 * (c[0] - c[4]);
    float u = fmaf(H2, c[2],  H6 * c[6]);
    float v = fmaf(H6, c[2], -H2 * c[6]);
    float E0 = p + u, E1 = m + v, E2 = m - v, E3 = p - u;
    float O0 = fmaf(H1, c[1], fmaf( H3, c[3], fmaf( H5, c[5],  H7 * c[7])));
    float O1 = fmaf(H3, c[1], fmaf(-H7, c[3], fmaf(-H1, c[5], -H5 * c[7])));
    float O2 = fmaf(H5, c[1], fmaf(-H1, c[3], fmaf( H7, c[5],  H3 * c[7])));
    float O3 = fmaf(H7, c[1], fmaf(-H5, c[3], fmaf( H3, c[5], -H1 * c[7])));
    r[0] = E0 + O0;  r[7] = E0 - O0;
    r[1] = E1 + O1;  r[6] = E1 - O1;
    r[2] = E2 + O2;  r[5] = E2 - O2;
    r[3] = E3 + O3;  r[4] = E3 - O3;
}

__global__ __launch_bounds__(128, 9)
void h264_dct_kernel(const float* __restrict__ x, float* __restrict__ out) {
    // CTA: 128 threads, strip = 8 rows x 128 cols = 16 8x8 blocks.
    // Thread t owns one 8-pixel column; bgr stay in registers for the
    // epilogue (R3 showed reloading them regresses). Butterfly transforms
    // in registers; smem only for two conflict-free 8x8 transposes.
    __shared__ float s1[8][129];
    __shared__ float s2[8][129];
    __shared__ float sQ[8][9];

    const int t = threadIdx.x;
    if (t < 64) {
        int k = t >> 3, u = t & 7;
        // QF=28 >= 25 -> scale = 144 ; q = max(base*144/50, 1)
        sQ[k][u] = fmaxf((c_qbase[t] * 144.0f) / 50.0f, 1.0f);
    }

    const int g = t >> 3;         // block index within strip
    const int l = t & 7;          // lane within block
    const int col = blockIdx.x * 128 + t;
    const size_t base = (size_t)blockIdx.z * (3 * (size_t)PLANE)
                      + (size_t)(blockIdx.y * 8) * IMG_W + col;

    float vb[8], vg[8], vr[8], a[8], w[8];

    // Load BGR once (registers), form luma column.
    #pragma unroll
    for (int i = 0; i < 8; ++i) {
        size_t p = base + (size_t)i * IMG_W;
        vb[i] = x[p];
        vg[i] = x[p + PLANE];
        vr[i] = x[p + 2 * PLANE];
        a[i]  = 0.114f * vb[i] + 0.587f * vg[i] + 0.299f * vr[i];
    }

    // Vertical DCT
    dct8(a, w);

    // Transpose 1: thread -> owns row l of block g  (bank-conflict-free)
    #pragma unroll
    for (int k = 0; k < 8; ++k) s1[k][t] = w[k];
    __syncthreads();
    #pragma unroll
    for (int j = 0; j < 8; ++j) a[j] = s1[l][(g << 3) + j];

    // Horizontal DCT + quantize (round-half-even, q + 1e-8 as in reference)
    dct8(a, w);
    float cq[8];
    #pragma unroll
    for (int u = 0; u < 8; ++u) {
        float q = sQ[l][u];
        cq[u] = rintf(w[u] / (q + 1e-8f)) * q;
    }

    // Horizontal IDCT
    idct8(cq, w);

    // Transpose 2 (separate buffer -> single barrier)
    #pragma unroll
    for (int b = 0; b < 8; ++b) s2[l][(g << 3) + b] = w[b];
    __syncthreads();
    #pragma unroll
    for (int i = 0; i < 8; ++i) a[i] = s2[i][t];

    // Vertical IDCT
    float rec[8];
    idct8(a, rec);

    // Epilogue: delta redistribution from register-resident bgr.
    #pragma unroll
    for (int i = 0; i < 8; ++i) {
        float yv = 0.114f * vb[i] + 0.587f * vg[i] + 0.299f * vr[i];
        float yd = rec[i] - yv;
        size_t p = base + (size_t)i * IMG_W;
        out[p]             = fminf(fmaxf(vb[i] + 0.114f * yd, 0.0f), 255.0f);
        out[p + PLANE]     = fminf(fmaxf(vg[i] + 0.587f * yd, 0.0f), 255.0f);
        out[p + 2 * PLANE] = fminf(fmaxf(vr[i] + 0.299f * yd, 0.0f), 255.0f);
    }
}

extern "C" void kernel_launch(void* const* d_in, const int* in_sizes, int n_in,
                              void* d_out, int out_size) {
    const float* x = (const float*)d_in[0];
    float* out = (float*)d_out;

    int B = in_sizes[0] / (3 * PLANE);

    dim3 block(128, 1, 1);
    dim3 grid(IMG_W / 128, IMG_H / 8, B);   // 15 x 135 x B
    h264_dct_kernel<<<grid, block>>>(x, out);
}